// round 2
// baseline (speedup 1.0000x reference)
#include <cuda_runtime.h>
#include <math.h>

#define T_    2048
#define HID_  4096
#define H_    32
#define HKV_  8
#define D_    128
#define NQKV_ 6144         // (H + 2*HKV) * D
#define WIN_  1024

// ---------------- scratch (static device arrays; no allocs allowed) --------
__device__ float g_qkv[T_ * NQKV_];       // 50.3 MB
__device__ float g_q  [T_ * H_   * D_];   // 33.5 MB (normed + roped Q)
__device__ float g_k  [T_ * HKV_ * D_];   //  8.4 MB (normed + roped K)
__device__ float g_attn[T_ * H_  * D_];   // 33.5 MB

// ---------------- fp32 tiled GEMM: C[M,N] = A[M,K] @ B[K,N], row-major -----
// BM=BN=128, BK=8, 256 threads, 8x8 micro-tile per thread.
// Requires M%128==0, N%128==0, K%8==0 (true for all three calls).
__global__ __launch_bounds__(256, 2)
void sgemm_kernel(const float* __restrict__ A, const float* __restrict__ B,
                  float* __restrict__ C, int M, int N, int K) {
  __shared__ float As[8][128];   // transposed A tile: As[k][m]
  __shared__ float Bs[8][128];
  const int tid  = threadIdx.x;
  const int cRow = blockIdx.y * 128;
  const int cCol = blockIdx.x * 128;
  const int aRow = tid >> 1;
  const int aCol = (tid & 1) << 2;
  const int bRow = tid >> 5;
  const int bCol = (tid & 31) << 2;
  const int ty   = tid >> 4;
  const int tx   = tid & 15;

  float acc[8][8];
#pragma unroll
  for (int i = 0; i < 8; i++)
#pragma unroll
    for (int j = 0; j < 8; j++) acc[i][j] = 0.f;

  const float* Aptr = A + (size_t)(cRow + aRow) * K + aCol;
  const float* Bptr = B + (size_t)bRow * N + cCol + bCol;

  for (int k0 = 0; k0 < K; k0 += 8) {
    float4 a4 = *(const float4*)(Aptr + k0);
    As[aCol + 0][aRow] = a4.x;
    As[aCol + 1][aRow] = a4.y;
    As[aCol + 2][aRow] = a4.z;
    As[aCol + 3][aRow] = a4.w;
    *(float4*)&Bs[bRow][bCol] = *(const float4*)(Bptr + (size_t)k0 * N);
    __syncthreads();
#pragma unroll
    for (int kk = 0; kk < 8; kk++) {
      float ar[8], br[8];
      *(float4*)(ar)     = *(const float4*)&As[kk][ty * 8];
      *(float4*)(ar + 4) = *(const float4*)&As[kk][ty * 8 + 4];
      *(float4*)(br)     = *(const float4*)&Bs[kk][tx * 8];
      *(float4*)(br + 4) = *(const float4*)&Bs[kk][tx * 8 + 4];
#pragma unroll
      for (int i = 0; i < 8; i++)
#pragma unroll
        for (int j = 0; j < 8; j++)
          acc[i][j] = fmaf(ar[i], br[j], acc[i][j]);
    }
    __syncthreads();
  }

#pragma unroll
  for (int i = 0; i < 8; i++) {
    float* cp = C + (size_t)(cRow + ty * 8 + i) * N + cCol + tx * 8;
    *(float4*)(cp)     = make_float4(acc[i][0], acc[i][1], acc[i][2], acc[i][3]);
    *(float4*)(cp + 4) = make_float4(acc[i][4], acc[i][5], acc[i][6], acc[i][7]);
  }
}

// ---------------- fused RMSNorm + NeoX RoPE --------------------------------
// grid (T, H + HKV), 128 threads; one (token, head) row per block.
// qkv column for head h (q or k section) is simply h*D + d.
__global__ void norm_rope_kernel(const float* __restrict__ qkv,
                                 const int*   __restrict__ positions,
                                 const float* __restrict__ qw,
                                 const float* __restrict__ kw,
                                 float* __restrict__ qout,
                                 float* __restrict__ kout) {
  const int t    = blockIdx.x;
  const int head = blockIdx.y;          // 0..H-1 = q heads, H..H+HKV-1 = k heads
  const int d    = threadIdx.x;         // 0..127
  const bool isq = head < H_;

  float x = qkv[(size_t)t * NQKV_ + head * D_ + d];

  __shared__ float red[4];
  __shared__ float xs[D_];
  float ss = x * x;
#pragma unroll
  for (int m = 16; m; m >>= 1) ss += __shfl_xor_sync(0xffffffffu, ss, m);
  if ((d & 31) == 0) red[d >> 5] = ss;
  __syncthreads();
  float var = (red[0] + red[1] + red[2] + red[3]) * (1.0f / D_);
  float r = rsqrtf(var + 1e-5f);
  const float* w = isq ? qw : kw;
  xs[d] = x * r * w[d];
  __syncthreads();

  int   pos = positions[t];
  int   i   = d & 63;                    // frequency index
  double inv_freq = pow(1000000.0, -(double)i / 64.0);
  double ang = (double)pos * inv_freq;
  double sd, cd;
  sincos(ang, &sd, &cd);
  float c = (float)cd, s = (float)sd;

  float o;
  if (d < 64) o = xs[d] * c - xs[d + 64] * s;
  else        o = xs[d] * c + xs[d - 64] * s;

  if (isq) qout[((size_t)t * H_   + head)        * D_ + d] = o;
  else     kout[((size_t)t * HKV_ + (head - H_)) * D_ + d] = o;
}

// ---------------- sliding-window flash attention ---------------------------
// grid (T/64, H), 256 threads. 64-query tile x 64-key tiles, online softmax.
// Shared: Qs[128][68] (transposed, pre-scaled), Ks[128][68] (transposed,
// overlaid by P[64][64] after S is computed), Vs[64][128]. 100 KB total.
__global__ __launch_bounds__(256, 2)
void attn_kernel(const float* __restrict__ Q, const float* __restrict__ K,
                 const float* __restrict__ Vbase, float* __restrict__ O) {
  extern __shared__ float sm[];
  float* Qs = sm;                 // 128*68
  float* Ks = Qs + 128 * 68;      // 128*68 (>= 64*64 for P overlay)
  float* Vs = Ks + 128 * 68;      // 64*128
  float* Ps = Ks;

  const int qb  = blockIdx.x;     // query block, 0..31
  const int h   = blockIdx.y;     // head, 0..31
  const int kh  = h >> 2;         // kv head (H/HKV = 4)
  const int tid = threadIdx.x;
  const int tx  = tid & 15;       // key-group / d-group
  const int ty  = tid >> 4;       // query-group
  const int q0  = qb * 64;
  const float scale = 0.08838834764831845f;  // D^-0.5

  // Load Q tile (transposed, pre-scaled)
  for (int e = tid; e < 64 * 128; e += 256) {
    int qi = e >> 7, d = e & 127;
    Qs[d * 68 + qi] = Q[((size_t)(q0 + qi) * H_ + h) * D_ + d] * scale;
  }

  float m[4], l[4], acc[4][8];
#pragma unroll
  for (int i = 0; i < 4; i++) {
    m[i] = -1e30f; l[i] = 0.f;
#pragma unroll
    for (int j = 0; j < 8; j++) acc[i][j] = 0.f;
  }

  const int kb0 = (qb >= 16) ? (qb - 16) : 0;   // window = 1024 = 16 tiles
  for (int kb = kb0; kb <= qb; kb++) {
    __syncthreads();                            // protects Qs (1st iter) & Ks/Vs reuse
    const int k0 = kb * 64;
    for (int e = tid; e < 64 * 128; e += 256) {
      int kj = e >> 7, d = e & 127;
      Ks[d * 68 + kj]  = K[((size_t)(k0 + kj) * HKV_ + kh) * D_ + d];
      Vs[kj * 128 + d] = Vbase[(size_t)(k0 + kj) * NQKV_ + kh * D_ + d];
    }
    __syncthreads();

    // S = Q K^T  (4x4 micro-tile per thread)
    float s[4][4];
#pragma unroll
    for (int i = 0; i < 4; i++)
#pragma unroll
      for (int j = 0; j < 4; j++) s[i][j] = 0.f;
#pragma unroll 4
    for (int d = 0; d < 128; d++) {
      float4 a = *(const float4*)&Qs[d * 68 + ty * 4];
      float4 b = *(const float4*)&Ks[d * 68 + tx * 4];
      float ar[4] = {a.x, a.y, a.z, a.w};
      float br[4] = {b.x, b.y, b.z, b.w};
#pragma unroll
      for (int i = 0; i < 4; i++)
#pragma unroll
        for (int j = 0; j < 4; j++)
          s[i][j] = fmaf(ar[i], br[j], s[i][j]);
    }

    // causal + window mask
#pragma unroll
    for (int i = 0; i < 4; i++) {
      int qi_g = q0 + ty * 4 + i;
#pragma unroll
      for (int j = 0; j < 4; j++) {
        int kj_g = k0 + tx * 4 + j;
        if (kj_g > qi_g || (qi_g - kj_g) >= WIN_) s[i][j] = -1e30f;
      }
    }

    // online softmax: row reductions across the 16 lanes sharing ty
    float sc[4];
#pragma unroll
    for (int i = 0; i < 4; i++) {
      float tm = fmaxf(fmaxf(s[i][0], s[i][1]), fmaxf(s[i][2], s[i][3]));
#pragma unroll
      for (int o = 8; o >= 1; o >>= 1)
        tm = fmaxf(tm, __shfl_xor_sync(0xffffffffu, tm, o));
      float mn = fmaxf(m[i], tm);
      float rs = 0.f;
#pragma unroll
      for (int j = 0; j < 4; j++) { s[i][j] = __expf(s[i][j] - mn); rs += s[i][j]; }
#pragma unroll
      for (int o = 8; o >= 1; o >>= 1)
        rs += __shfl_xor_sync(0xffffffffu, rs, o);
      sc[i] = __expf(m[i] - mn);
      l[i]  = l[i] * sc[i] + rs;
      m[i]  = mn;
    }

    __syncthreads();   // everyone done reading Ks -> safe to overlay P
#pragma unroll
    for (int i = 0; i < 4; i++)
      *(float4*)&Ps[(ty * 4 + i) * 64 + tx * 4] =
          make_float4(s[i][0], s[i][1], s[i][2], s[i][3]);
    __syncthreads();

    // O = O*scale + P @ V   (each thread: 4 queries x 8 dims, tx*8..)
#pragma unroll
    for (int i = 0; i < 4; i++)
#pragma unroll
      for (int j = 0; j < 8; j++) acc[i][j] *= sc[i];

#pragma unroll 2
    for (int j = 0; j < 64; j++) {
      float4 v0 = *(const float4*)&Vs[j * 128 + tx * 8];
      float4 v1 = *(const float4*)&Vs[j * 128 + tx * 8 + 4];
      float vv[8] = {v0.x, v0.y, v0.z, v0.w, v1.x, v1.y, v1.z, v1.w};
      float p0 = Ps[(ty * 4 + 0) * 64 + j];
      float p1 = Ps[(ty * 4 + 1) * 64 + j];
      float p2 = Ps[(ty * 4 + 2) * 64 + j];
      float p3 = Ps[(ty * 4 + 3) * 64 + j];
#pragma unroll
      for (int dd = 0; dd < 8; dd++) {
        acc[0][dd] = fmaf(p0, vv[dd], acc[0][dd]);
        acc[1][dd] = fmaf(p1, vv[dd], acc[1][dd]);
        acc[2][dd] = fmaf(p2, vv[dd], acc[2][dd]);
        acc[3][dd] = fmaf(p3, vv[dd], acc[3][dd]);
      }
    }
  }

  // final normalize + write
#pragma unroll
  for (int i = 0; i < 4; i++) {
    float inv = 1.f / l[i];
    int qi_g = q0 + ty * 4 + i;
    float* op = &O[((size_t)qi_g * H_ + h) * D_ + tx * 8];
    *(float4*)(op)     = make_float4(acc[i][0] * inv, acc[i][1] * inv,
                                     acc[i][2] * inv, acc[i][3] * inv);
    *(float4*)(op + 4) = make_float4(acc[i][4] * inv, acc[i][5] * inv,
                                     acc[i][6] * inv, acc[i][7] * inv);
  }
}

// ---------------- launch ---------------------------------------------------
extern "C" void kernel_launch(void* const* d_in, const int* in_sizes, int n_in,
                              void* d_out, int out_size) {
  const int*   positions = (const int*)  d_in[0];
  const float* hidden    = (const float*)d_in[1];
  const float* w_qkv     = (const float*)d_in[2];
  const float* q_norm_w  = (const float*)d_in[3];
  const float* k_norm_w  = (const float*)d_in[4];
  const float* w_o       = (const float*)d_in[5];
  float* out = (float*)d_out;

  float *qkv, *q, *k, *attn;
  cudaGetSymbolAddress((void**)&qkv,  g_qkv);
  cudaGetSymbolAddress((void**)&q,    g_q);
  cudaGetSymbolAddress((void**)&k,    g_k);
  cudaGetSymbolAddress((void**)&attn, g_attn);

  // 1) qkv = hidden @ w_qkv        [2048,4096]x[4096,6144]
  sgemm_kernel<<<dim3(NQKV_ / 128, T_ / 128), 256>>>(hidden, w_qkv, qkv,
                                                     T_, NQKV_, HID_);
  // 2) rmsnorm + rope
  norm_rope_kernel<<<dim3(T_, H_ + HKV_), 128>>>(qkv, positions, q_norm_w,
                                                 k_norm_w, q, k);
  // 3) sliding-window attention
  cudaFuncSetAttribute(attn_kernel,
                       cudaFuncAttributeMaxDynamicSharedMemorySize, 102400);
  attn_kernel<<<dim3(T_ / 64, H_), 256, 102400>>>(q, k,
                                                  qkv + (H_ + HKV_) * D_, attn);
  // 4) out = attn @ w_o            [2048,4096]x[4096,4096]
  sgemm_kernel<<<dim3(HID_ / 128, T_ / 128), 256>>>(attn, w_o, out,
                                                    T_, HID_, HID_);
}

// round 3
// speedup vs baseline: 3.0826x; 3.0826x over previous
#include <cuda_runtime.h>
#include <math.h>
#include <stdint.h>

#define T_    2048
#define HID_  4096
#define H_    32
#define HKV_  8
#define D_    128
#define NQKV_ 6144
#define WIN_  1024

// ---------------- scratch ---------------------------------------------------
__device__ float g_qkv [T_ * NQKV_];
__device__ float g_q   [T_ * H_ * D_];        // [t][h][d]
__device__ float g_kt  [HKV_ * D_ * T_];      // [kh][d][t]  (transposed K)
__device__ float g_attn[T_ * H_ * D_];
__device__ float g_cos [T_ * 64];
__device__ float g_sin [T_ * 64];

// ---------------- helpers ---------------------------------------------------
__device__ __forceinline__ uint32_t f2tf32(float f) {
  uint32_t u;
  asm("cvt.rna.tf32.f32 %0, %1;" : "=r"(u) : "f"(f));
  return u;
}
__device__ __forceinline__ void mma_tf32(float* d, const uint32_t* a,
                                         const uint32_t* b) {
  asm volatile(
      "mma.sync.aligned.m16n8k8.row.col.f32.tf32.tf32.f32 "
      "{%0,%1,%2,%3}, {%4,%5,%6,%7}, {%8,%9}, {%0,%1,%2,%3};"
      : "+f"(d[0]), "+f"(d[1]), "+f"(d[2]), "+f"(d[3])
      : "r"(a[0]), "r"(a[1]), "r"(a[2]), "r"(a[3]), "r"(b[0]), "r"(b[1]));
}

// ---------------- tf32 GEMM: C[M,N] = A[M,K] @ B[K,N] ----------------------
// BM=BN=128, BK=32, 256 threads (8 warps, 2x4 warp grid, 64x32 warp tile)
__global__ __launch_bounds__(256, 2)
void tf32_gemm(const float* __restrict__ A, const float* __restrict__ B,
               float* __restrict__ C, int M, int N, int K) {
  __shared__ uint32_t As[128][36];
  __shared__ uint32_t Bs[32][132];
  const int tid  = threadIdx.x;
  const int lane = tid & 31;
  const int warp = tid >> 5;
  const int wm   = warp & 1;     // 0..1  (64-row slab)
  const int wn   = warp >> 1;    // 0..3  (32-col slab)
  const int cRow = blockIdx.y * 128;
  const int cCol = blockIdx.x * 128;

  float acc[4][4][4];
#pragma unroll
  for (int mt = 0; mt < 4; mt++)
#pragma unroll
    for (int nt = 0; nt < 4; nt++)
#pragma unroll
      for (int r = 0; r < 4; r++) acc[mt][nt][r] = 0.f;

  const int aRow = tid >> 1, aCol = (tid & 1) * 16;
  const int bRow = tid >> 3, bCol = (tid & 7) * 16;
  const float* Ap = A + (size_t)(cRow + aRow) * K + aCol;
  const float* Bp = B + (size_t)bRow * N + cCol + bCol;

  for (int k0 = 0; k0 < K; k0 += 32) {
#pragma unroll
    for (int i = 0; i < 4; i++) {
      float4 v = *(const float4*)(Ap + k0 + i * 4);
      As[aRow][aCol + i * 4 + 0] = f2tf32(v.x);
      As[aRow][aCol + i * 4 + 1] = f2tf32(v.y);
      As[aRow][aCol + i * 4 + 2] = f2tf32(v.z);
      As[aRow][aCol + i * 4 + 3] = f2tf32(v.w);
    }
#pragma unroll
    for (int i = 0; i < 4; i++) {
      float4 v = *(const float4*)(Bp + (size_t)k0 * N + i * 4);
      Bs[bRow][bCol + i * 4 + 0] = f2tf32(v.x);
      Bs[bRow][bCol + i * 4 + 1] = f2tf32(v.y);
      Bs[bRow][bCol + i * 4 + 2] = f2tf32(v.z);
      Bs[bRow][bCol + i * 4 + 3] = f2tf32(v.w);
    }
    __syncthreads();
#pragma unroll
    for (int ks = 0; ks < 4; ks++) {
      uint32_t af[4][4], bf[4][2];
#pragma unroll
      for (int mt = 0; mt < 4; mt++) {
        int r = wm * 64 + mt * 16 + (lane >> 2);
        int c = ks * 8 + (lane & 3);
        af[mt][0] = As[r][c];
        af[mt][1] = As[r + 8][c];
        af[mt][2] = As[r][c + 4];
        af[mt][3] = As[r + 8][c + 4];
      }
#pragma unroll
      for (int nt = 0; nt < 4; nt++) {
        int r = ks * 8 + (lane & 3);
        int c = wn * 32 + nt * 8 + (lane >> 2);
        bf[nt][0] = Bs[r][c];
        bf[nt][1] = Bs[r + 4][c];
      }
#pragma unroll
      for (int mt = 0; mt < 4; mt++)
#pragma unroll
        for (int nt = 0; nt < 4; nt++) mma_tf32(acc[mt][nt], af[mt], bf[nt]);
    }
    __syncthreads();
  }

#pragma unroll
  for (int mt = 0; mt < 4; mt++) {
    int r = cRow + wm * 64 + mt * 16 + (lane >> 2);
#pragma unroll
    for (int nt = 0; nt < 4; nt++) {
      int c = cCol + wn * 32 + nt * 8 + (lane & 3) * 2;
      *(float2*)&C[(size_t)r * N + c] =
          make_float2(acc[mt][nt][0], acc[mt][nt][1]);
      *(float2*)&C[(size_t)(r + 8) * N + c] =
          make_float2(acc[mt][nt][2], acc[mt][nt][3]);
    }
  }
}

// ---------------- RoPE table (fp64 once, tiny) ------------------------------
__global__ void rope_table_kernel(const int* __restrict__ positions) {
  int t = blockIdx.x, i = threadIdx.x;  // i in 0..63
  double inv_freq = pow(1000000.0, -(double)i / 64.0);
  double ang = (double)positions[t] * inv_freq;
  double sd, cd;
  sincos(ang, &sd, &cd);
  g_cos[t * 64 + i] = (float)cd;
  g_sin[t * 64 + i] = (float)sd;
}

// ---------------- fused RMSNorm + NeoX RoPE --------------------------------
// grid (T, H+HKV), 128 threads. K written transposed: [kh][d][t].
__global__ void norm_rope_kernel(const float* __restrict__ qkv,
                                 const float* __restrict__ qw,
                                 const float* __restrict__ kw,
                                 float* __restrict__ qout,
                                 float* __restrict__ ktout) {
  const int t    = blockIdx.x;
  const int head = blockIdx.y;
  const int d    = threadIdx.x;
  const bool isq = head < H_;

  float x = qkv[(size_t)t * NQKV_ + head * D_ + d];

  __shared__ float red[4];
  __shared__ float xs[D_];
  float ss = x * x;
#pragma unroll
  for (int m = 16; m; m >>= 1) ss += __shfl_xor_sync(0xffffffffu, ss, m);
  if ((d & 31) == 0) red[d >> 5] = ss;
  __syncthreads();
  float var = (red[0] + red[1] + red[2] + red[3]) * (1.0f / D_);
  float r = rsqrtf(var + 1e-5f);
  const float* w = isq ? qw : kw;
  xs[d] = x * r * w[d];
  __syncthreads();

  float c = g_cos[t * 64 + (d & 63)];
  float s = g_sin[t * 64 + (d & 63)];
  float o;
  if (d < 64) o = xs[d] * c - xs[d + 64] * s;
  else        o = xs[d] * c + xs[d - 64] * s;

  if (isq) qout[((size_t)t * H_ + head) * D_ + d] = o;
  else     ktout[((size_t)(head - H_) * D_ + d) * T_ + t] = o;
}

// ---------------- tf32 MMA flash attention ----------------------------------
// grid (T/64, H), 128 threads (4 warps, 16 query rows each).
// smem: Kt[128][68] tf32, Vs[64][136] f32, Ps[64][76] f32  (89,088 B)
#define KT_S 68
#define VS_S 136
#define PS_S 76
__global__ __launch_bounds__(128)
void attn_mma_kernel(const float* __restrict__ Q,
                     const float* __restrict__ Ktg,   // [HKV][D][T]
                     const float* __restrict__ Vbase, // qkv v section
                     float* __restrict__ O) {
  extern __shared__ float smf[];
  uint32_t* Kt = (uint32_t*)smf;          // 128*68
  float*    Vs = smf + 128 * KT_S;        // 64*136
  float*    Ps = Vs + 64 * VS_S;          // 64*76

  const int qb = blockIdx.x, h = blockIdx.y, kh = h >> 2;
  const int tid = threadIdx.x, lane = tid & 31, w = tid >> 5;
  const int q0 = qb * 64;
  const int r0 = lane >> 2, r1 = r0 + 8;
  const int qi0 = q0 + w * 16 + r0;
  const int qi1 = q0 + w * 16 + r1;
  const float scale = 0.08838834764831845f;

  // Q fragments in registers (pre-scaled, tf32)
  uint32_t qf[16][4];
  {
    const float* q0p = Q + ((size_t)qi0 * H_ + h) * D_;
    const float* q1p = Q + ((size_t)qi1 * H_ + h) * D_;
#pragma unroll
    for (int ks = 0; ks < 16; ks++) {
      int c = ks * 8 + (lane & 3);
      qf[ks][0] = f2tf32(q0p[c] * scale);
      qf[ks][1] = f2tf32(q1p[c] * scale);
      qf[ks][2] = f2tf32(q0p[c + 4] * scale);
      qf[ks][3] = f2tf32(q1p[c + 4] * scale);
    }
  }

  float accO[16][4];
#pragma unroll
  for (int nt = 0; nt < 16; nt++)
#pragma unroll
    for (int r = 0; r < 4; r++) accO[nt][r] = 0.f;
  float m0 = -1e30f, m1 = -1e30f, l0 = 0.f, l1 = 0.f;

  const int kb0 = (qb >= 16) ? (qb - 16) : 0;
  for (int kb = kb0; kb <= qb; kb++) {
    __syncthreads();
    const int k0 = kb * 64;
    // K tile: Kt[d][key] from [kh][d][t] — coalesced, tf32-converted
    for (int e = tid; e < 2048; e += 128) {
      int d = e >> 4, kq = (e & 15) * 4;
      float4 v = *(const float4*)(Ktg + ((size_t)kh * D_ + d) * T_ + k0 + kq);
      Kt[d * KT_S + kq + 0] = f2tf32(v.x);
      Kt[d * KT_S + kq + 1] = f2tf32(v.y);
      Kt[d * KT_S + kq + 2] = f2tf32(v.z);
      Kt[d * KT_S + kq + 3] = f2tf32(v.w);
    }
    // V tile: Vs[key][d]
    for (int e = tid; e < 2048; e += 128) {
      int kj = e >> 5, dq = (e & 31) * 4;
      float4 v = *(const float4*)(Vbase + (size_t)(k0 + kj) * NQKV_ +
                                  kh * D_ + dq);
      Vs[kj * VS_S + dq + 0] = v.x;
      Vs[kj * VS_S + dq + 1] = v.y;
      Vs[kj * VS_S + dq + 2] = v.z;
      Vs[kj * VS_S + dq + 3] = v.w;
    }
    __syncthreads();

    // S = Q @ K^T   (per warp: 16 x 64)
    float s[8][4];
#pragma unroll
    for (int nt = 0; nt < 8; nt++)
#pragma unroll
      for (int r = 0; r < 4; r++) s[nt][r] = 0.f;
#pragma unroll
    for (int ks = 0; ks < 16; ks++) {
      int rr = ks * 8 + (lane & 3);
#pragma unroll
      for (int nt = 0; nt < 8; nt++) {
        int cc = nt * 8 + (lane >> 2);
        uint32_t bf[2] = {Kt[rr * KT_S + cc], Kt[(rr + 4) * KT_S + cc]};
        mma_tf32(s[nt], qf[ks], bf);
      }
    }

    // mask
#pragma unroll
    for (int nt = 0; nt < 8; nt++) {
#pragma unroll
      for (int j = 0; j < 4; j++) {
        int kj_g = k0 + nt * 8 + (lane & 3) * 2 + (j & 1);
        int qi = (j < 2) ? qi0 : qi1;
        if (kj_g > qi || (qi - kj_g) >= WIN_) s[nt][j] = -1e30f;
      }
    }

    // online softmax (rows r0: regs 0,1; rows r1: regs 2,3)
    float tm0 = -1e30f, tm1 = -1e30f;
#pragma unroll
    for (int nt = 0; nt < 8; nt++) {
      tm0 = fmaxf(tm0, fmaxf(s[nt][0], s[nt][1]));
      tm1 = fmaxf(tm1, fmaxf(s[nt][2], s[nt][3]));
    }
    tm0 = fmaxf(tm0, __shfl_xor_sync(0xffffffffu, tm0, 1));
    tm0 = fmaxf(tm0, __shfl_xor_sync(0xffffffffu, tm0, 2));
    tm1 = fmaxf(tm1, __shfl_xor_sync(0xffffffffu, tm1, 1));
    tm1 = fmaxf(tm1, __shfl_xor_sync(0xffffffffu, tm1, 2));
    float mn0 = fmaxf(m0, tm0), mn1 = fmaxf(m1, tm1);
    float sum0 = 0.f, sum1 = 0.f;
#pragma unroll
    for (int nt = 0; nt < 8; nt++) {
      s[nt][0] = __expf(s[nt][0] - mn0); sum0 += s[nt][0];
      s[nt][1] = __expf(s[nt][1] - mn0); sum0 += s[nt][1];
      s[nt][2] = __expf(s[nt][2] - mn1); sum1 += s[nt][2];
      s[nt][3] = __expf(s[nt][3] - mn1); sum1 += s[nt][3];
    }
    sum0 += __shfl_xor_sync(0xffffffffu, sum0, 1);
    sum0 += __shfl_xor_sync(0xffffffffu, sum0, 2);
    sum1 += __shfl_xor_sync(0xffffffffu, sum1, 1);
    sum1 += __shfl_xor_sync(0xffffffffu, sum1, 2);
    float sc0 = __expf(m0 - mn0), sc1 = __expf(m1 - mn1);
    l0 = l0 * sc0 + sum0; l1 = l1 * sc1 + sum1;
    m0 = mn0; m1 = mn1;
#pragma unroll
    for (int nt = 0; nt < 16; nt++) {
      accO[nt][0] *= sc0; accO[nt][1] *= sc0;
      accO[nt][2] *= sc1; accO[nt][3] *= sc1;
    }

    // P -> per-warp smem (no cross-warp dependence)
    float* pr = Ps + (size_t)(w * 16) * PS_S;
#pragma unroll
    for (int nt = 0; nt < 8; nt++) {
      int c = nt * 8 + (lane & 3) * 2;
      *(float2*)&pr[r0 * PS_S + c] = make_float2(s[nt][0], s[nt][1]);
      *(float2*)&pr[r1 * PS_S + c] = make_float2(s[nt][2], s[nt][3]);
    }
    __syncwarp();

    // O += P @ V
#pragma unroll
    for (int ks = 0; ks < 8; ks++) {
      int c = ks * 8 + (lane & 3);
      uint32_t af[4];
      af[0] = __float_as_uint(pr[r0 * PS_S + c]);
      af[1] = __float_as_uint(pr[r1 * PS_S + c]);
      af[2] = __float_as_uint(pr[r0 * PS_S + c + 4]);
      af[3] = __float_as_uint(pr[r1 * PS_S + c + 4]);
      int rr = ks * 8 + (lane & 3);
#pragma unroll
      for (int nt = 0; nt < 16; nt++) {
        int cc = nt * 8 + (lane >> 2);
        uint32_t bf[2] = {__float_as_uint(Vs[rr * VS_S + cc]),
                          __float_as_uint(Vs[(rr + 4) * VS_S + cc])};
        mma_tf32(accO[nt], af, bf);
      }
    }
  }

  // normalize + write
  float inv0 = 1.f / l0, inv1 = 1.f / l1;
  float* o0 = O + ((size_t)qi0 * H_ + h) * D_;
  float* o1 = O + ((size_t)qi1 * H_ + h) * D_;
#pragma unroll
  for (int nt = 0; nt < 16; nt++) {
    int c = nt * 8 + (lane & 3) * 2;
    *(float2*)&o0[c] = make_float2(accO[nt][0] * inv0, accO[nt][1] * inv0);
    *(float2*)&o1[c] = make_float2(accO[nt][2] * inv1, accO[nt][3] * inv1);
  }
}

// ---------------- launch ---------------------------------------------------
extern "C" void kernel_launch(void* const* d_in, const int* in_sizes, int n_in,
                              void* d_out, int out_size) {
  const int*   positions = (const int*)  d_in[0];
  const float* hidden    = (const float*)d_in[1];
  const float* w_qkv     = (const float*)d_in[2];
  const float* q_norm_w  = (const float*)d_in[3];
  const float* k_norm_w  = (const float*)d_in[4];
  const float* w_o       = (const float*)d_in[5];
  float* out = (float*)d_out;

  float *qkv, *q, *kt, *attn;
  cudaGetSymbolAddress((void**)&qkv,  g_qkv);
  cudaGetSymbolAddress((void**)&q,    g_q);
  cudaGetSymbolAddress((void**)&kt,   g_kt);
  cudaGetSymbolAddress((void**)&attn, g_attn);

  // 0) rope table
  rope_table_kernel<<<T_, 64>>>(positions);
  // 1) qkv = hidden @ w_qkv
  tf32_gemm<<<dim3(NQKV_ / 128, T_ / 128), 256>>>(hidden, w_qkv, qkv,
                                                  T_, NQKV_, HID_);
  // 2) rmsnorm + rope (K transposed to [kh][d][t])
  norm_rope_kernel<<<dim3(T_, H_ + HKV_), 128>>>(qkv, q_norm_w, k_norm_w,
                                                 q, kt);
  // 3) attention
  static int smset = 0;
  if (!smset) {
    cudaFuncSetAttribute(attn_mma_kernel,
                         cudaFuncAttributeMaxDynamicSharedMemorySize,
                         (128 * KT_S + 64 * VS_S + 64 * PS_S) * 4);
    smset = 1;
  }
  attn_mma_kernel<<<dim3(T_ / 64, H_), 128,
                    (128 * KT_S + 64 * VS_S + 64 * PS_S) * 4>>>(
      q, kt, qkv + (H_ + HKV_) * D_, attn);
  // 4) out = attn @ w_o
  tf32_gemm<<<dim3(HID_ / 128, T_ / 128), 256>>>(attn, w_o, out,
                                                 T_, HID_, HID_);
}